// round 15
// baseline (speedup 1.0000x reference)
#include <cuda_runtime.h>
#include <cuda_fp16.h>
#include <cstdint>

#define D       1024
#define NROW    4096
#define BM      128
#define BN      128
#define BK      64                 // 64 fp16 = 128 B per row-chunk
#define NCHUNK  (D / BK)           // 16
#define ROWB    128                // bytes per smem row (XOR-swizzled)
#define ARRB    (128 * ROWB)       // 16 KB per operand per stage
#define STAGEB  (2 * ARRB)         // 32 KB
#define NSTAGE  3
#define SMEM_TOTAL (NSTAGE * STAGEB)   // 98304 B -> 2 CTAs/SM
#define NTILES  ((NROW / BM) * (NROW / BN))   // 1024
#define GRID    304                // 2 CTAs x 152 SMs (GB300), persistent

// ---- scratch (allocation-guard-safe __device__ globals) ----
__device__ __align__(256) __half g_xh[NROW * D];
__device__ __align__(256) __half g_yh[NROW * D];
__device__ __align__(16)  float  g_rnx[NROW];   // 20 / ||x_i||  (temp folded)
__device__ __align__(16)  float  g_rny[NROW];   // 1 / ||y_j||

// ---- helpers ----
__device__ __forceinline__ uint32_t smem_u32(const void* p) {
    uint32_t a;
    asm("{ .reg .u64 t; cvta.to.shared.u64 t, %1; cvt.u32.u64 %0, t; }" : "=r"(a) : "l"(p));
    return a;
}
__device__ __forceinline__ void cp16(uint32_t s, const void* g) {
    asm volatile("cp.async.cg.shared.global [%0], [%1], 16;" :: "r"(s), "l"(g));
}
#define CP_COMMIT() asm volatile("cp.async.commit_group;" ::: "memory")
template <int N>
__device__ __forceinline__ void cp_wait() {
    asm volatile("cp.async.wait_group %0;" :: "n"(N) : "memory");
}
__device__ __forceinline__ void ldsm4(uint32_t* r, uint32_t addr) {
    asm volatile("ldmatrix.sync.aligned.m8n8.x4.shared.b16 {%0,%1,%2,%3}, [%4];"
                 : "=r"(r[0]), "=r"(r[1]), "=r"(r[2]), "=r"(r[3]) : "r"(addr));
}
__device__ __forceinline__ void mma_fp16(float* d, const uint32_t* a, const uint32_t* b) {
    asm volatile(
        "mma.sync.aligned.m16n8k16.row.col.f32.f16.f16.f32 "
        "{%0,%1,%2,%3}, {%4,%5,%6,%7}, {%8,%9}, {%0,%1,%2,%3};"
        : "+f"(d[0]), "+f"(d[1]), "+f"(d[2]), "+f"(d[3])
        : "r"(a[0]), "r"(a[1]), "r"(a[2]), "r"(a[3]), "r"(b[0]), "r"(b[1]));
}

// ---- prep: 2 rows per warp, load-all-then-store (16-deep MLP) ----
__global__ __launch_bounds__(256) void prep_kernel(const float* __restrict__ x,
                                                   const float* __restrict__ y) {
    const int w = threadIdx.x >> 5;
    const int lane = threadIdx.x & 31;
    const int wid = blockIdx.x * 8 + w;          // 0..4095 (pair index)
    const bool isy = (wid >= NROW / 2);
    const int rb = (isy ? wid - NROW / 2 : wid) * 2;
    const float* src = isy ? y : x;
    __half* dh = isy ? g_yh : g_xh;
    float* dn = isy ? g_rny : g_rnx;
    const float num = isy ? 1.0f : 20.0f;

    const float4* p4 = reinterpret_cast<const float4*>(src + (size_t)rb * D);

    float4 v[2][8];
    #pragma unroll
    for (int rr = 0; rr < 2; rr++)
        #pragma unroll
        for (int j = 0; j < 8; j++)
            v[rr][j] = p4[rr * (D / 4) + lane + 32 * j];   // 16-deep MLP

    #pragma unroll
    for (int rr = 0; rr < 2; rr++) {
        uint2* dst = reinterpret_cast<uint2*>(dh + (size_t)(rb + rr) * D);
        float s = 0.f;
        #pragma unroll
        for (int j = 0; j < 8; j++) {
            const float4 t = v[rr][j];
            s += t.x * t.x + t.y * t.y + t.z * t.z + t.w * t.w;
            __half2 h0 = __floats2half2_rn(t.x, t.y);
            __half2 h1 = __floats2half2_rn(t.z, t.w);
            uint2 hv;
            hv.x = *reinterpret_cast<uint32_t*>(&h0);
            hv.y = *reinterpret_cast<uint32_t*>(&h1);
            __stcg(&dst[lane + 32 * j], hv);     // L2-only: consumed cross-SM
        }
        #pragma unroll
        for (int o = 16; o > 0; o >>= 1) s += __shfl_down_sync(0xffffffffu, s, o);
        if (lane == 0) dn[rb + rr] = num * rsqrtf(s);
    }
}

// ---- main GEMM: persistent CTAs; next-tile fill hidden behind epilogue ----
__global__ __launch_bounds__(256, 2) void cosgemm_kernel(float* __restrict__ O) {
    extern __shared__ char smem[];
    const uint32_t sb = smem_u32(smem);
    const int tid = threadIdx.x;
    const int w = tid >> 5, lane = tid & 31;
    const int wm = w >> 2, wn = w & 3;      // 2 x 4 warp grid, warp tile 64x32
    const uint32_t lx = (uint32_t)(lane & 7);

    const int r0 = tid >> 3, c0 = tid & 7;
    const uint32_t soff0 = (uint32_t)(r0 * ROWB + ((c0 ^ (r0 & 7)) * 16));

    const uint32_t arow = (uint32_t)((wm * 64 + (lane & 15)) * ROWB);
    const uint32_t brow = (uint32_t)((wn * 32 + (lane & 7) + ((lane >> 4) << 3)) * ROWB);
    const uint32_t acat = (uint32_t)(lane >> 4);
    const uint32_t bcat = (uint32_t)((lane >> 3) & 1);

    uint32_t afrag[2][4][4], bfrag[2][2][4];
    float acc[4][4][4];

#define LOAD_CHUNK(i) do {                                                      \
        const uint32_t st_ = sb + (uint32_t)((i) % NSTAGE) * STAGEB;            \
        const __half* a_ = pA + (i) * BK;                                       \
        const __half* b_ = pB + (i) * BK;                                       \
        _Pragma("unroll")                                                       \
        for (int k_ = 0; k_ < 4; k_++)                                          \
            cp16(st_ + soff0 + 4096u * k_, a_ + (size_t)(32 * k_) * D);         \
        _Pragma("unroll")                                                       \
        for (int k_ = 0; k_ < 4; k_++)                                          \
            cp16(st_ + ARRB + soff0 + 4096u * k_, b_ + (size_t)(32 * k_) * D);  \
        CP_COMMIT();                                                            \
    } while (0)

#define LDSM_STEP(st_, s_, buf_) do {                                           \
        const uint32_t aco_ = (((uint32_t)(s_) * 2 + acat) ^ lx) * 16;          \
        const uint32_t bco_ = (((uint32_t)(s_) * 2 + bcat) ^ lx) * 16;          \
        _Pragma("unroll")                                                       \
        for (int mi_ = 0; mi_ < 4; mi_++)                                       \
            ldsm4(afrag[buf_][mi_], (st_) + arow + (uint32_t)(mi_ * 16 * ROWB) + aco_); \
        _Pragma("unroll")                                                       \
        for (int np_ = 0; np_ < 2; np_++)                                       \
            ldsm4(bfrag[buf_][np_], (st_) + ARRB + brow + (uint32_t)(np_ * 16 * ROWB) + bco_); \
    } while (0)

#define MMA_ALL(buf_) do {                                                      \
        _Pragma("unroll")                                                       \
        for (int mi_ = 0; mi_ < 4; mi_++)                                       \
            _Pragma("unroll")                                                   \
            for (int ni_ = 0; ni_ < 4; ni_++)                                   \
                mma_fp16(acc[mi_][ni_], afrag[buf_][mi_],                       \
                         &bfrag[buf_][ni_ >> 1][(ni_ & 1) * 2]);                \
    } while (0)

    int tile = blockIdx.x;
    int row0 = (tile >> 5) * BM;
    int col0 = (tile & 31) * BN;
    const __half* pA = g_xh + (size_t)(row0 + r0) * D + c0 * 8;
    const __half* pB = g_yh + (size_t)(col0 + r0) * D + c0 * 8;

    // first tile: cold fill
    LOAD_CHUNK(0);
    LOAD_CHUNK(1);
    LOAD_CHUNK(2);

    while (true) {
        #pragma unroll
        for (int mi = 0; mi < 4; mi++)
            #pragma unroll
            for (int ni = 0; ni < 4; ni++)
                #pragma unroll
                for (int r = 0; r < 4; r++) acc[mi][ni][r] = 0.f;

        cp_wait<2>();
        __syncthreads();
        LDSM_STEP(sb, 0, 0);     // chunk 0, k-step 0 -> buffer 0

        #pragma unroll
        for (int i = 0; i < NCHUNK; i++) {
            const uint32_t st = sb + (uint32_t)(i % NSTAGE) * STAGEB;

            #pragma unroll
            for (int s = 0; s < 3; s++) {
                LDSM_STEP(st, s + 1, (s & 1) ^ 1);
                MMA_ALL(s & 1);
            }

            if (i < NCHUNK - 1) {
                if (i + 3 < NCHUNK) {
                    cp_wait<1>();
                    __syncthreads();
                    LOAD_CHUNK(i + 3);
                } else if (i == NCHUNK - 3) {
                    cp_wait<1>();
                    __syncthreads();
                } else {             // i == NCHUNK - 2: all groups drained
                    cp_wait<0>();
                    __syncthreads();
                }
                LDSM_STEP(sb + (uint32_t)((i + 1) % NSTAGE) * STAGEB, 0, 0);
            }

            MMA_ALL(1);              // k-step 3
        }

        const int erow = row0, ecol = col0;      // epilogue coords for THIS tile
        const int next = tile + GRID;

        // all smem reads of this tile retired -> refill for next tile,
        // hidden behind the epilogue stores below
        __syncthreads();
        if (next < NTILES) {
            row0 = (next >> 5) * BM;
            col0 = (next & 31) * BN;
            pA = g_xh + (size_t)(row0 + r0) * D + c0 * 8;
            pB = g_yh + (size_t)(col0 + r0) * D + c0 * 8;
            LOAD_CHUNK(0);
            LOAD_CHUNK(1);
            LOAD_CHUNK(2);
        }

        // fused cosine epilogue
        const int rbase = erow + wm * 64 + (lane >> 2);
        const int cbase = ecol + wn * 32 + (lane & 3) * 2;
        #pragma unroll
        for (int mi = 0; mi < 4; mi++) {
            const int r = rbase + mi * 16;
            const float n0 = __ldg(g_rnx + r);
            const float n1 = __ldg(g_rnx + r + 8);
            #pragma unroll
            for (int ni = 0; ni < 4; ni++) {
                const int c = cbase + ni * 8;
                const float2 ry = __ldg(reinterpret_cast<const float2*>(g_rny + c));
                float2 o0, o1;
                o0.x = acc[mi][ni][0] * n0 * ry.x;
                o0.y = acc[mi][ni][1] * n0 * ry.y;
                o1.x = acc[mi][ni][2] * n1 * ry.x;
                o1.y = acc[mi][ni][3] * n1 * ry.y;
                __stcs(reinterpret_cast<float2*>(O + (size_t)r * NROW + c),       o0);
                __stcs(reinterpret_cast<float2*>(O + (size_t)(r + 8) * NROW + c), o1);
            }
        }

        if (next >= NTILES) break;
        tile = next;
    }
}

extern "C" void kernel_launch(void* const* d_in, const int* in_sizes, int n_in,
                              void* d_out, int out_size) {
    const float* x = (const float*)d_in[0];
    const float* y = (const float*)d_in[1];
    float* o = (float*)d_out;
    (void)in_sizes; (void)n_in; (void)out_size;

    prep_kernel<<<NROW / 8, 256>>>(x, y);

    cudaFuncSetAttribute(cosgemm_kernel, cudaFuncAttributeMaxDynamicSharedMemorySize, SMEM_TOTAL);
    cosgemm_kernel<<<GRID, 256, SMEM_TOTAL>>>(o);
}

// round 16
// speedup vs baseline: 1.0388x; 1.0388x over previous
#include <cuda_runtime.h>
#include <cuda_fp16.h>
#include <cstdint>

#define D       1024
#define NROW    4096
#define BM      128
#define BN      128
#define BK      64                 // 64 fp16 = 128 B per row-chunk
#define NCHUNK  (D / BK)           // 16
#define ROWB    128                // bytes per smem row (XOR-swizzled)
#define ARRB    (128 * ROWB)       // 16 KB per operand per stage
#define STAGEB  (2 * ARRB)         // 32 KB
#define NSTAGE  3
#define SMEM_TOTAL (NSTAGE * STAGEB)   // 98304 B -> 2 CTAs/SM

// ---- scratch (allocation-guard-safe __device__ globals) ----
__device__ __align__(256) __half g_xh[NROW * D];
__device__ __align__(256) __half g_yh[NROW * D];
__device__ __align__(16)  float  g_rnx[NROW];   // 20 / ||x_i||  (temp folded)
__device__ __align__(16)  float  g_rny[NROW];   // 1 / ||y_j||

// ---- helpers ----
__device__ __forceinline__ uint32_t smem_u32(const void* p) {
    uint32_t a;
    asm("{ .reg .u64 t; cvta.to.shared.u64 t, %1; cvt.u32.u64 %0, t; }" : "=r"(a) : "l"(p));
    return a;
}
__device__ __forceinline__ void cp16(uint32_t s, const void* g) {
    asm volatile("cp.async.cg.shared.global [%0], [%1], 16;" :: "r"(s), "l"(g));
}
#define CP_COMMIT() asm volatile("cp.async.commit_group;" ::: "memory")
template <int N>
__device__ __forceinline__ void cp_wait() {
    asm volatile("cp.async.wait_group %0;" :: "n"(N) : "memory");
}
__device__ __forceinline__ void ldsm4(uint32_t* r, uint32_t addr) {
    asm volatile("ldmatrix.sync.aligned.m8n8.x4.shared.b16 {%0,%1,%2,%3}, [%4];"
                 : "=r"(r[0]), "=r"(r[1]), "=r"(r[2]), "=r"(r[3]) : "r"(addr));
}
__device__ __forceinline__ void mma_fp16(float* d, const uint32_t* a, const uint32_t* b) {
    asm volatile(
        "mma.sync.aligned.m16n8k16.row.col.f32.f16.f16.f32 "
        "{%0,%1,%2,%3}, {%4,%5,%6,%7}, {%8,%9}, {%0,%1,%2,%3};"
        : "+f"(d[0]), "+f"(d[1]), "+f"(d[2]), "+f"(d[3])
        : "r"(a[0]), "r"(a[1]), "r"(a[2]), "r"(a[3]), "r"(b[0]), "r"(b[1]));
}

// ---- prep: 2 rows per warp, load-all-then-store (16-deep MLP) ----
__global__ __launch_bounds__(256) void prep_kernel(const float* __restrict__ x,
                                                   const float* __restrict__ y) {
    const int w = threadIdx.x >> 5;
    const int lane = threadIdx.x & 31;
    const int wid = blockIdx.x * 8 + w;          // 0..4095 (pair index)
    const bool isy = (wid >= NROW / 2);
    const int rb = (isy ? wid - NROW / 2 : wid) * 2;
    const float* src = isy ? y : x;
    __half* dh = isy ? g_yh : g_xh;
    float* dn = isy ? g_rny : g_rnx;
    const float num = isy ? 1.0f : 20.0f;

    const float4* p4 = reinterpret_cast<const float4*>(src + (size_t)rb * D);

    float4 v[2][8];
    #pragma unroll
    for (int rr = 0; rr < 2; rr++)
        #pragma unroll
        for (int j = 0; j < 8; j++)
            v[rr][j] = p4[rr * (D / 4) + lane + 32 * j];   // 16-deep MLP

    #pragma unroll
    for (int rr = 0; rr < 2; rr++) {
        uint2* dst = reinterpret_cast<uint2*>(dh + (size_t)(rb + rr) * D);
        float s = 0.f;
        #pragma unroll
        for (int j = 0; j < 8; j++) {
            const float4 t = v[rr][j];
            s += t.x * t.x + t.y * t.y + t.z * t.z + t.w * t.w;
            __half2 h0 = __floats2half2_rn(t.x, t.y);
            __half2 h1 = __floats2half2_rn(t.z, t.w);
            uint2 hv;
            hv.x = *reinterpret_cast<uint32_t*>(&h0);
            hv.y = *reinterpret_cast<uint32_t*>(&h1);
            __stcg(&dst[lane + 32 * j], hv);     // L2-only: consumed cross-SM
        }
        #pragma unroll
        for (int o = 16; o > 0; o >>= 1) s += __shfl_down_sync(0xffffffffu, s, o);
        if (lane == 0) dn[rb + rr] = num * rsqrtf(s);
    }
}

// ---- main GEMM: fp16 mma.sync, fragment double-buffer (converged core) ----
__global__ __launch_bounds__(256, 2) void cosgemm_kernel(float* __restrict__ O) {
    extern __shared__ char smem[];
    const uint32_t sb = smem_u32(smem);
    const int tid = threadIdx.x;
    const int w = tid >> 5, lane = tid & 31;
    const int wm = w >> 2, wn = w & 3;      // 2 x 4 warp grid, warp tile 64x32
    const int row0 = blockIdx.y * BM;
    const int col0 = blockIdx.x * BN;
    const uint32_t lx = (uint32_t)(lane & 7);

    const int r0 = tid >> 3, c0 = tid & 7;
    const uint32_t soff0 = (uint32_t)(r0 * ROWB + ((c0 ^ (r0 & 7)) * 16));
    const __half* pA = g_xh + (size_t)(row0 + r0) * D + c0 * 8;
    const __half* pB = g_yh + (size_t)(col0 + r0) * D + c0 * 8;

    const uint32_t arow = (uint32_t)((wm * 64 + (lane & 15)) * ROWB);
    const uint32_t brow = (uint32_t)((wn * 32 + (lane & 7) + ((lane >> 4) << 3)) * ROWB);
    const uint32_t acat = (uint32_t)(lane >> 4);
    const uint32_t bcat = (uint32_t)((lane >> 3) & 1);

    float acc[4][4][4];
    #pragma unroll
    for (int mi = 0; mi < 4; mi++)
        #pragma unroll
        for (int ni = 0; ni < 4; ni++)
            #pragma unroll
            for (int r = 0; r < 4; r++) acc[mi][ni][r] = 0.f;

    uint32_t afrag[2][4][4], bfrag[2][2][4];

#define LOAD_CHUNK(i) do {                                                      \
        const uint32_t st_ = sb + (uint32_t)((i) % NSTAGE) * STAGEB;            \
        const __half* a_ = pA + (i) * BK;                                       \
        const __half* b_ = pB + (i) * BK;                                       \
        _Pragma("unroll")                                                       \
        for (int k_ = 0; k_ < 4; k_++)                                          \
            cp16(st_ + soff0 + 4096u * k_, a_ + (size_t)(32 * k_) * D);         \
        _Pragma("unroll")                                                       \
        for (int k_ = 0; k_ < 4; k_++)                                          \
            cp16(st_ + ARRB + soff0 + 4096u * k_, b_ + (size_t)(32 * k_) * D);  \
        CP_COMMIT();                                                            \
    } while (0)

#define LDSM_STEP(st_, s_, buf_) do {                                           \
        const uint32_t aco_ = (((uint32_t)(s_) * 2 + acat) ^ lx) * 16;          \
        const uint32_t bco_ = (((uint32_t)(s_) * 2 + bcat) ^ lx) * 16;          \
        _Pragma("unroll")                                                       \
        for (int mi_ = 0; mi_ < 4; mi_++)                                       \
            ldsm4(afrag[buf_][mi_], (st_) + arow + (uint32_t)(mi_ * 16 * ROWB) + aco_); \
        _Pragma("unroll")                                                       \
        for (int np_ = 0; np_ < 2; np_++)                                       \
            ldsm4(bfrag[buf_][np_], (st_) + ARRB + brow + (uint32_t)(np_ * 16 * ROWB) + bco_); \
    } while (0)

#define MMA_ALL(buf_) do {                                                      \
        _Pragma("unroll")                                                       \
        for (int mi_ = 0; mi_ < 4; mi_++)                                       \
            _Pragma("unroll")                                                   \
            for (int ni_ = 0; ni_ < 4; ni_++)                                   \
                mma_fp16(acc[mi_][ni_], afrag[buf_][mi_],                       \
                         &bfrag[buf_][ni_ >> 1][(ni_ & 1) * 2]);                \
    } while (0)

    LOAD_CHUNK(0);
    LOAD_CHUNK(1);
    LOAD_CHUNK(2);
    cp_wait<2>();
    __syncthreads();
    LDSM_STEP(sb, 0, 0);     // chunk 0, k-step 0 -> buffer 0

    #pragma unroll
    for (int i = 0; i < NCHUNK; i++) {
        const uint32_t st = sb + (uint32_t)(i % NSTAGE) * STAGEB;

        #pragma unroll
        for (int s = 0; s < 3; s++) {
            LDSM_STEP(st, s + 1, (s & 1) ^ 1);
            MMA_ALL(s & 1);
        }

        if (i < NCHUNK - 1) {
            if (i + 3 < NCHUNK) {
                cp_wait<1>();
                __syncthreads();
                LOAD_CHUNK(i + 3);
            } else if (i == NCHUNK - 3) {
                cp_wait<1>();
                __syncthreads();
            } else {             // i == NCHUNK - 2
                cp_wait<0>();
                __syncthreads();
            }
            LDSM_STEP(sb + (uint32_t)((i + 1) % NSTAGE) * STAGEB, 0, 0);
        }

        MMA_ALL(1);              // k-step 3
    }

    // fused cosine epilogue; streaming stores keep operands resident in L2
    const int rbase = row0 + wm * 64 + (lane >> 2);
    const int cbase = col0 + wn * 32 + (lane & 3) * 2;
    #pragma unroll
    for (int mi = 0; mi < 4; mi++) {
        const int r = rbase + mi * 16;
        const float n0 = __ldg(g_rnx + r);
        const float n1 = __ldg(g_rnx + r + 8);
        #pragma unroll
        for (int ni = 0; ni < 4; ni++) {
            const int c = cbase + ni * 8;
            const float2 ry = __ldg(reinterpret_cast<const float2*>(g_rny + c));
            float2 o0, o1;
            o0.x = acc[mi][ni][0] * n0 * ry.x;
            o0.y = acc[mi][ni][1] * n0 * ry.y;
            o1.x = acc[mi][ni][2] * n1 * ry.x;
            o1.y = acc[mi][ni][3] * n1 * ry.y;
            __stcs(reinterpret_cast<float2*>(O + (size_t)r * NROW + c),       o0);
            __stcs(reinterpret_cast<float2*>(O + (size_t)(r + 8) * NROW + c), o1);
        }
    }
}

extern "C" void kernel_launch(void* const* d_in, const int* in_sizes, int n_in,
                              void* d_out, int out_size) {
    const float* x = (const float*)d_in[0];
    const float* y = (const float*)d_in[1];
    float* o = (float*)d_out;
    (void)in_sizes; (void)n_in; (void)out_size;

    prep_kernel<<<NROW / 8, 256>>>(x, y);

    cudaFuncSetAttribute(cosgemm_kernel, cudaFuncAttributeMaxDynamicSharedMemorySize, SMEM_TOTAL);
    cosgemm_kernel<<<dim3(NROW / BN, NROW / BM), 256, SMEM_TOTAL>>>(o);
}